// round 17
// baseline (speedup 1.0000x reference)
#include <cuda_runtime.h>
#include <cstdint>

#define Hh 16
#define Bb 4
#define Ss 1024
#define Dd 1024
#define dhd 64
#define LN_EPS 1e-5f
#define SD (Bb * Ss * Dd)

// Scratch (__device__ globals; allocation-free rule)
__device__ float g_QKV[3 * SD];              // Q,K,V projections
__device__ float g_Vt[Hh * Bb * dhd * Ss];   // V^T per (h,b): [64][1024] K-contig
__device__ float g_concat[SD];
__device__ float g_pre[SD];
__device__ float g_WT[4 * Dd * Dd];          // WqT,WkT,WvT,WoT (K-contig, tf32)

// ---------------------------------------------------------------------------
// Portable PTX helpers
// ---------------------------------------------------------------------------
__device__ __forceinline__ void cp16(uint32_t dst, const float* src) {
    uint64_t g = __cvta_generic_to_global((void*)src);
    asm volatile("cp.async.cg.shared.global [%0], [%1], 16;" :: "r"(dst), "l"(g));
}
__device__ __forceinline__ uint32_t smem_u32(const void* p) {
    uint32_t a;
    asm("{ .reg .u64 t; cvta.to.shared.u64 t, %1; cvt.u32.u64 %0, t; }" : "=r"(a) : "l"(p));
    return a;
}
__device__ __forceinline__ float tf32r(float x) {
    float r;
    asm("cvt.rna.tf32.f32 %0, %1;" : "=f"(r) : "f"(x));
    return r;
}
__device__ __forceinline__ float ex2a(float x) {          // 2^x, approx
    float r;
    asm("ex2.approx.f32 %0, %1;" : "=f"(r) : "f"(x));
    return r;
}
#define SCL 0.18033688f   // 0.125 * log2(e):  exp(s/8) == 2^(s*SCL)

__device__ __forceinline__ void mma8(float* c, const uint32_t* a, const uint32_t* b) {
    asm volatile(
        "mma.sync.aligned.m16n8k8.row.col.f32.tf32.tf32.f32 "
        "{%0,%1,%2,%3}, {%4,%5,%6,%7}, {%8,%9}, {%0,%1,%2,%3};"
        : "+f"(c[0]), "+f"(c[1]), "+f"(c[2]), "+f"(c[3])
        : "r"(a[0]), "r"(a[1]), "r"(a[2]), "r"(a[3]), "r"(b[0]), "r"(b[1]));
}
#define LDM_X4(r0, r1, r2, r3, addr)                                         \
    asm volatile("ldmatrix.sync.aligned.m8n8.x4.shared.b16 {%0,%1,%2,%3}, [%4];" \
        : "=r"(r0), "=r"(r1), "=r"(r2), "=r"(r3) : "r"(addr))
#define CP_COMMIT() asm volatile("cp.async.commit_group;" ::: "memory")
#define CP_WAIT0()  asm volatile("cp.async.wait_group 0;" ::: "memory")
#define CP_WAIT1()  asm volatile("cp.async.wait_group 1;" ::: "memory")
#define CP_WAIT2()  asm volatile("cp.async.wait_group 2;" ::: "memory")
#define CP_WAIT3()  asm volatile("cp.async.wait_group 3;" ::: "memory")

// ---------------------------------------------------------------------------
// tf32 GEMM (projections, out-proj): C = alpha*A@B^T (+R). BK=32, 3-stage
// cp.async, ONE barrier per chunk, register double-buffered ldmatrix frags.
// ---------------------------------------------------------------------------
template <int BM, int BN>
__global__ __launch_bounds__(256, 2)
void mma_gemm(const float* __restrict__ A0, const float* __restrict__ A1,
              const float* __restrict__ A2, int lda,
              const float* __restrict__ Bm, int ldb, long long zsB,
              float* __restrict__ Cm, int ldc, long long zsC,
              const float* __restrict__ R, float alpha, int NC)
{
    constexpr int WN_ = 32, WM_ = 64;
    constexpr int WARPS_N = BN / WN_;
    constexpr int MT = WM_ / 16, NT = WN_ / 8;
    constexpr int PAD = 36;
    constexpr int ASTG = BM * PAD, BSTG = BN * PAD, STG = ASTG + BSTG;

    extern __shared__ float smem[];
    const uint32_t s0 = smem_u32(smem);

    const int tid = threadIdx.x, w = tid >> 5, lane = tid & 31;
    const int wm = w / WARPS_N, wn = w % WARPS_N;
    const int g = lane >> 2, tq = lane & 3;

    const uint32_t aoffB = (uint32_t)(((lane & 15) * PAD + (lane >> 4) * 4) * 4);
    const uint32_t boffB = (uint32_t)(
        (((lane & 7) + ((lane >> 4) << 3)) * PAD + ((lane >> 3) & 1) * 4) * 4);

    const int z = blockIdx.z;
    const float* Az = (z == 0) ? A0 : (z == 1) ? A1 : A2;
    const float* Ap = Az + (long long)blockIdx.y * 128 * lda;
    const float* Bp = Bm + z * zsB + (long long)blockIdx.x * 128 * ldb;
    float* Cp = Cm + z * zsC + (long long)blockIdx.y * 128 * ldc + blockIdx.x * 128;
    const float* Rp = R ? R + (long long)blockIdx.y * 128 * ldc + blockIdx.x * 128 : nullptr;

    auto loadc = [&](int c, int p) {
        const uint32_t base = s0 + (uint32_t)p * STG * 4;
        const float* a = Ap + c * 32;
        #pragma unroll
        for (int i = 0; i < BM * 8 / 256; i++) {
            int idx = tid + i * 256, row = idx >> 3, kq = idx & 7;
            cp16(base + (uint32_t)(row * PAD + kq * 4) * 4, a + (long long)row * lda + kq * 4);
        }
        const float* b = Bp + c * 32;
        const uint32_t bb = base + (uint32_t)ASTG * 4;
        #pragma unroll
        for (int i = 0; i < BN * 8 / 256; i++) {
            int idx = tid + i * 256, row = idx >> 3, kq = idx & 7;
            cp16(bb + (uint32_t)(row * PAD + kq * 4) * 4, b + (long long)row * ldb + kq * 4);
        }
        CP_COMMIT();
    };

    float acc[MT][NT][4];
    #pragma unroll
    for (int i = 0; i < MT; i++)
        #pragma unroll
        for (int j = 0; j < NT; j++)
            acc[i][j][0] = acc[i][j][1] = acc[i][j][2] = acc[i][j][3] = 0.f;

    uint32_t afr[2][MT][4], bfr[2][NT][2];

    loadc(0, 0);
    loadc(1, 1);

    for (int c = 0; c < NC; c++) {
        const int p = c - (c / 3) * 3;
        if (c + 1 < NC) CP_WAIT1();
        else            CP_WAIT0();
        __syncthreads();
        if (c + 2 < NC) loadc(c + 2, (c + 2) - ((c + 2) / 3) * 3);

        const uint32_t aBase = s0 + (uint32_t)p * STG * 4;
        const uint32_t bBase = aBase + (uint32_t)ASTG * 4;

        auto ldfrag = [&](int ks, int buf) {
            const int k = ks * 8;
            #pragma unroll
            for (int mt = 0; mt < MT; mt++) {
                uint32_t ad = aBase + (uint32_t)(((wm * WM_ + mt * 16) * PAD + k) * 4) + aoffB;
                LDM_X4(afr[buf][mt][0], afr[buf][mt][1], afr[buf][mt][2], afr[buf][mt][3], ad);
            }
            #pragma unroll
            for (int ntp = 0; ntp < NT / 2; ntp++) {
                uint32_t bd = bBase + (uint32_t)(((wn * WN_ + ntp * 16) * PAD + k) * 4) + boffB;
                LDM_X4(bfr[buf][2 * ntp][0], bfr[buf][2 * ntp][1],
                       bfr[buf][2 * ntp + 1][0], bfr[buf][2 * ntp + 1][1], bd);
            }
        };

        ldfrag(0, 0);
        #pragma unroll
        for (int ks = 0; ks < 4; ks++) {
            const int buf = ks & 1;
            if (ks < 3) ldfrag(ks + 1, buf ^ 1);
            #pragma unroll
            for (int mt = 0; mt < MT; mt++)
                #pragma unroll
                for (int nt = 0; nt < NT; nt++)
                    mma8(acc[mt][nt], afr[buf][mt], bfr[buf][nt]);
        }
    }

    #pragma unroll
    for (int mt = 0; mt < MT; mt++) {
        #pragma unroll
        for (int nt = 0; nt < NT; nt++) {
            const int r = wm * WM_ + mt * 16 + g;
            const int cc = wn * WN_ + nt * 8 + 2 * tq;
            float2 v0 = make_float2(acc[mt][nt][0] * alpha, acc[mt][nt][1] * alpha);
            float2 v1 = make_float2(acc[mt][nt][2] * alpha, acc[mt][nt][3] * alpha);
            if (Rp) {
                float2 r0 = *(const float2*)(Rp + (long long)r * ldc + cc);
                float2 r1 = *(const float2*)(Rp + (long long)(r + 8) * ldc + cc);
                v0.x += r0.x; v0.y += r0.y; v1.x += r1.x; v1.y += r1.y;
            }
            *(float2*)(Cp + (long long)r * ldc + cc) = v0;
            *(float2*)(Cp + (long long)(r + 8) * ldc + cc) = v1;
        }
    }
}

// ---------------------------------------------------------------------------
// Fused causal attention: scores + softmax + PV, two-pass flash style.
// Pass 1: 3-buffer K ring (3rd buffer aliases the idle P region), distance-2
// prefetch, wait_group 1. Pass 2: split K/V waits (S starts when K lands;
// V wait deferred to just before the PV MMAs). Heavy-first dispatch.
// ---------------------------------------------------------------------------
#define PK 68     // K-tile row pad (64+4)
#define PVV 132   // V-tile row pad (128+4)
#define PP 132    // P-tile row pad (128+4)
#define OFF_K0 0
#define OFF_K1 8704
#define OFF_V0 17408
#define OFF_V1 25856
#define OFF_P  34304
#define FUSED_SMEM ((OFF_P + 128 * PP) * 4)   // 204800 B

__global__ __launch_bounds__(256, 1)
void fused_attn(const float* __restrict__ Q, const float* __restrict__ K,
                const float* __restrict__ Vt, float* __restrict__ attn,
                float* __restrict__ Oc)
{
    extern __shared__ float sm[];
    const uint32_t s0 = smem_u32(sm);

    const int qt = 7 - blockIdx.y;          // heavy-first
    const int z = blockIdx.x;
    const int h = z >> 2, b = z & 3;
    const int tid = threadIdx.x, w = tid >> 5, lane = tid & 31;
    const int g = lane >> 2, tq = lane & 3;
    const int NTk = qt + 1;

    const float* Qp = Q + ((long long)b * Ss + qt * 128) * Dd + h * dhd;
    const float* Kp = K + (long long)b * Ss * Dd + h * dhd;
    const float* Vp = Vt + (long long)z * dhd * Ss;
    float* attnP = attn + (long long)z * Ss * Ss + (long long)(qt * 128) * Ss;
    float* outP  = Oc + ((long long)b * Ss + qt * 128) * Dd + h * dhd;

    const uint32_t aoffP = (uint32_t)(((lane & 15) * PP + (lane >> 4) * 4) * 4);
    const uint32_t boffK = (uint32_t)(
        (((lane & 7) + ((lane >> 4) << 3)) * PK + ((lane >> 3) & 1) * 4) * 4);
    const uint32_t boffV = (uint32_t)(
        (((lane & 7) + ((lane >> 4) << 3)) * PVV + ((lane >> 3) & 1) * 4) * 4);

    auto loadK = [&](int kt, uint32_t off) {
        #pragma unroll
        for (int i = 0; i < 8; i++) {
            int idx = tid + i * 256, row = idx >> 4, c = idx & 15;
            cp16(s0 + (off + (uint32_t)(row * PK + c * 4)) * 4,
                 Kp + (long long)(kt * 128 + row) * Dd + c * 4);
        }
        CP_COMMIT();
    };
    auto loadV = [&](int kt, uint32_t off) {
        #pragma unroll
        for (int i = 0; i < 8; i++) {
            int idx = tid + i * 256, row = idx >> 5, c = idx & 31;
            cp16(s0 + (off + (uint32_t)(row * PVV + c * 4)) * 4,
                 Vp + (long long)row * Ss + kt * 128 + c * 4);
        }
        CP_COMMIT();
    };

    // Prologue: stage Q (group 1), V0 (2), K0 (3), K1 (4, if present)
    #pragma unroll
    for (int i = 0; i < 8; i++) {
        int idx = tid + i * 256, row = idx >> 4, c = idx & 15;
        cp16(s0 + (OFF_P + (uint32_t)(row * PP + c * 4)) * 4,
             Qp + (long long)row * Dd + c * 4);
    }
    CP_COMMIT();
    loadV(0, OFF_V0);
    loadK(0, OFF_K0);
    if (NTk > 1) loadK(1, OFF_K1);

    // Zero-fill strict-upper attn tiles while the cp.async groups fly
    for (int kt = qt + 1; kt < 8; kt++) {
        float* base = attnP + kt * 128;
        for (int i = tid; i < 128 * 32; i += 256) {
            int row = i >> 5, c = i & 31;
            *(float4*)(base + (long long)row * Ss + c * 4) = make_float4(0.f, 0.f, 0.f, 0.f);
        }
    }

    if (NTk > 1) CP_WAIT3(); else CP_WAIT2();   // Q done
    __syncthreads();
    uint32_t qf[8][4];     // persistent Q A-fragments
    #pragma unroll
    for (int ks = 0; ks < 8; ks++)
        LDM_X4(qf[ks][0], qf[ks][1], qf[ks][2], qf[ks][3],
               s0 + (uint32_t)((OFF_P + w * 16 * PP + ks * 8) * 4) + aoffP);

    const int r0 = w * 16 + g, r1 = r0 + 8;
    float l0 = 0.f, l1 = 0.f;
    float sacc[16][4];

    // S-tile compute with half-slice double-buffered K fragments.
    auto computeS = [&](uint32_t kOff) {
        #pragma unroll
        for (int nt = 0; nt < 16; nt++)
            sacc[nt][0] = sacc[nt][1] = sacc[nt][2] = sacc[nt][3] = 0.f;
        uint32_t bf2[2][8][2];
        auto ldh = [&](int ks, int hh, int buf) {
            #pragma unroll
            for (int nb = 0; nb < 4; nb++) {
                int nbg = hh * 4 + nb;
                LDM_X4(bf2[buf][2 * nb][0], bf2[buf][2 * nb][1],
                       bf2[buf][2 * nb + 1][0], bf2[buf][2 * nb + 1][1],
                       s0 + (uint32_t)((kOff + nbg * 16 * PK + ks * 8) * 4) + boffK);
            }
        };
        ldh(0, 0, 0);
        int buf = 0;
        #pragma unroll
        for (int ks = 0; ks < 8; ks++) {
            #pragma unroll
            for (int hh = 0; hh < 2; hh++) {
                if (!(ks == 7 && hh == 1))
                    ldh(hh == 1 ? ks + 1 : ks, hh ^ 1, buf ^ 1);
                #pragma unroll
                for (int j = 0; j < 8; j++)
                    mma8(sacc[hh * 8 + j], qf[ks], bf2[buf][j]);
                buf ^= 1;
            }
        }
    };

    const uint32_t KBUF[3] = {OFF_K0, OFF_K1, OFF_P};

    // ---------------- PASS 1: row sums l (3-buffer K ring) ----------------
    for (int kt = 0; kt < NTk; kt++) {
        const uint32_t kOff = KBUF[kt % 3];
        if (kt + 1 < NTk) CP_WAIT1();
        else              CP_WAIT0();
        __syncthreads();
        if (kt + 2 < NTk) loadK(kt + 2, KBUF[(kt + 2) % 3]);

        computeS(kOff);

        float ts0 = 0.f, ts1 = 0.f;
        if (kt != qt) {
            #pragma unroll
            for (int nt = 0; nt < 16; nt++) {
                ts0 += ex2a(sacc[nt][0] * SCL) + ex2a(sacc[nt][1] * SCL);
                ts1 += ex2a(sacc[nt][2] * SCL) + ex2a(sacc[nt][3] * SCL);
            }
        } else {
            #pragma unroll
            for (int nt = 0; nt < 16; nt++) {
                const int j0 = 8 * nt + 2 * tq, j1 = j0 + 1;
                ts0 += ((j0 > r0) ? 0.f : ex2a(sacc[nt][0] * SCL))
                     + ((j1 > r0) ? 0.f : ex2a(sacc[nt][1] * SCL));
                ts1 += ((j0 > r1) ? 0.f : ex2a(sacc[nt][2] * SCL))
                     + ((j1 > r1) ? 0.f : ex2a(sacc[nt][3] * SCL));
            }
        }
        ts0 += __shfl_xor_sync(0xffffffffu, ts0, 1);
        ts0 += __shfl_xor_sync(0xffffffffu, ts0, 2);
        ts1 += __shfl_xor_sync(0xffffffffu, ts1, 1);
        ts1 += __shfl_xor_sync(0xffffffffu, ts1, 2);
        l0 += ts0;
        l1 += ts1;
    }

    __syncthreads();
    loadK(0, OFF_K0);                    // pass-2 K0; V0 still resident
    const float invl0 = 1.0f / l0, invl1 = 1.0f / l1;

    float oacc[8][4];
    #pragma unroll
    for (int nt = 0; nt < 8; nt++)
        oacc[nt][0] = oacc[nt][1] = oacc[nt][2] = oacc[nt][3] = 0.f;

    // ---------------- PASS 2: probs -> attn + P@V (split K/V waits) -------
    for (int kt = 0; kt < NTk; kt++) {
        const int p = kt & 1;
        const uint32_t kOff = p ? OFF_K1 : OFF_K0;
        const uint32_t vOff = p ? OFF_V1 : OFF_V0;
        if (kt == 0) CP_WAIT0();   // only K0 outstanding
        else         CP_WAIT1();   // K(kt) done; V(kt) may still be in flight
        __syncthreads();
        if (kt + 1 < NTk) {
            loadK(kt + 1, p ? OFF_K0 : OFF_K1);
            loadV(kt + 1, p ? OFF_V0 : OFF_V1);
        }

        computeS(kOff);

        if (kt != qt) {
            #pragma unroll
            for (int nt = 0; nt < 16; nt++) {
                const int j0 = 8 * nt + 2 * tq;
                float p00 = ex2a(sacc[nt][0] * SCL) * invl0;
                float p01 = ex2a(sacc[nt][1] * SCL) * invl0;
                float p10 = ex2a(sacc[nt][2] * SCL) * invl1;
                float p11 = ex2a(sacc[nt][3] * SCL) * invl1;
                *(float2*)(attnP + (long long)r0 * Ss + kt * 128 + j0) = make_float2(p00, p01);
                *(float2*)(attnP + (long long)r1 * Ss + kt * 128 + j0) = make_float2(p10, p11);
                *(float2*)(sm + OFF_P + r0 * PP + j0) = make_float2(p00, p01);
                *(float2*)(sm + OFF_P + r1 * PP + j0) = make_float2(p10, p11);
            }
        } else {
            #pragma unroll
            for (int nt = 0; nt < 16; nt++) {
                const int j0 = 8 * nt + 2 * tq, j1 = j0 + 1;
                float p00 = (j0 > r0) ? 0.f : ex2a(sacc[nt][0] * SCL) * invl0;
                float p01 = (j1 > r0) ? 0.f : ex2a(sacc[nt][1] * SCL) * invl0;
                float p10 = (j0 > r1) ? 0.f : ex2a(sacc[nt][2] * SCL) * invl1;
                float p11 = (j1 > r1) ? 0.f : ex2a(sacc[nt][3] * SCL) * invl1;
                *(float2*)(attnP + (long long)r0 * Ss + kt * 128 + j0) = make_float2(p00, p01);
                *(float2*)(attnP + (long long)r1 * Ss + kt * 128 + j0) = make_float2(p10, p11);
                *(float2*)(sm + OFF_P + r0 * PP + j0) = make_float2(p00, p01);
                *(float2*)(sm + OFF_P + r1 * PP + j0) = make_float2(p10, p11);
            }
        }
        __syncwarp();   // own-warp rows only

        // V(kt) must be resident before the PV MMAs; allow the two newest
        // groups (K(kt+1), V(kt+1)) to remain in flight.
        if (kt + 1 < NTk) CP_WAIT2();
        else              CP_WAIT0();

        // PV with A + half-V register double-buffering
        {
            uint32_t ap2[2][4], vf2[2][4][2];
            auto ldA = [&](int ks, int buf) {
                LDM_X4(ap2[buf][0], ap2[buf][1], ap2[buf][2], ap2[buf][3],
                       s0 + (uint32_t)((OFF_P + w * 16 * PP + ks * 8) * 4) + aoffP);
            };
            auto ldVh = [&](int ks, int hh, int buf) {
                #pragma unroll
                for (int nb = 0; nb < 2; nb++) {
                    int nbg = hh * 2 + nb;
                    LDM_X4(vf2[buf][2 * nb][0], vf2[buf][2 * nb][1],
                           vf2[buf][2 * nb + 1][0], vf2[buf][2 * nb + 1][1],
                           s0 + (uint32_t)((vOff + nbg * 16 * PVV + ks * 8) * 4) + boffV);
                }
            };
            ldA(0, 0);
            ldVh(0, 0, 0);
            int ab = 0, vb = 0;
            #pragma unroll
            for (int ks = 0; ks < 16; ks++) {
                #pragma unroll
                for (int hh = 0; hh < 2; hh++) {
                    if (hh == 0) {
                        ldVh(ks, 1, vb ^ 1);
                    } else if (ks < 15) {
                        ldA(ks + 1, ab ^ 1);
                        ldVh(ks + 1, 0, vb ^ 1);
                    }
                    #pragma unroll
                    for (int j = 0; j < 4; j++)
                        mma8(oacc[hh * 4 + j], ap2[ab], vf2[vb][j]);
                    vb ^= 1;
                }
                ab ^= 1;
            }
        }
    }

    #pragma unroll
    for (int nt = 0; nt < 8; nt++) {
        const int cc = 8 * nt + 2 * tq;
        *(float2*)(outP + (long long)r0 * Dd + cc) = make_float2(oacc[nt][0], oacc[nt][1]);
        *(float2*)(outP + (long long)r1 * Dd + cc) = make_float2(oacc[nt][2], oacc[nt][3]);
    }
}

// ---------------------------------------------------------------------------
__global__ void transpose_w_k(const float* __restrict__ W0, const float* __restrict__ W1,
                              const float* __restrict__ W2, const float* __restrict__ W3,
                              float* __restrict__ O)
{
    __shared__ float t[32][33];
    const float* W = blockIdx.z == 0 ? W0 : blockIdx.z == 1 ? W1 : blockIdx.z == 2 ? W2 : W3;
    float* Oz = O + (long long)blockIdx.z * Dd * Dd;
    const int x0 = blockIdx.x * 32, y0 = blockIdx.y * 32;
    const int tx = threadIdx.x, ty0 = threadIdx.y;
    #pragma unroll
    for (int j = 0; j < 4; j++) {
        int ty = ty0 + j * 8;
        t[ty][tx] = tf32r(W[(long long)(y0 + ty) * Dd + x0 + tx]);
    }
    __syncthreads();
    #pragma unroll
    for (int j = 0; j < 4; j++) {
        int ty = ty0 + j * 8;
        Oz[(long long)(x0 + ty) * Dd + y0 + tx] = t[tx][ty];
    }
}

__global__ void transpose_v_k(const float* __restrict__ V, float* __restrict__ Vt)
{
    __shared__ float t[32][33];
    const int s0 = blockIdx.x * 32, d0 = blockIdx.y * 32, b = blockIdx.z;
    const int tx = threadIdx.x, ty0 = threadIdx.y;
    #pragma unroll
    for (int j = 0; j < 4; j++) {
        int ty = ty0 + j * 8;
        t[ty][tx] = V[((long long)b * Ss + s0 + ty) * Dd + d0 + tx];
    }
    __syncthreads();
    const int h = d0 >> 6, n0 = d0 & 63;
    #pragma unroll
    for (int j = 0; j < 4; j++) {
        int ty = ty0 + j * 8;
        Vt[((long long)(h * Bb + b) * dhd + n0 + ty) * Ss + s0 + tx] = t[tx][ty];
    }
}

__global__ void layernorm_k(const float* __restrict__ X,
                            const float* __restrict__ gamma,
                            const float* __restrict__ beta,
                            float* __restrict__ O)
{
    const long long row = blockIdx.x;
    const int tid = threadIdx.x;
    const float4 v = reinterpret_cast<const float4*>(X + (row << 10))[tid];

    float s  = v.x + v.y + v.z + v.w;
    float s2 = v.x * v.x + v.y * v.y + v.z * v.z + v.w * v.w;

    __shared__ float r1[8], r2[8];
    #pragma unroll
    for (int o = 16; o; o >>= 1) {
        s  += __shfl_xor_sync(0xffffffffu, s, o);
        s2 += __shfl_xor_sync(0xffffffffu, s2, o);
    }
    if ((tid & 31) == 0) { r1[tid >> 5] = s; r2[tid >> 5] = s2; }
    __syncthreads();
    s = 0.f; s2 = 0.f;
    #pragma unroll
    for (int i = 0; i < 8; i++) { s += r1[i]; s2 += r2[i]; }

    const float mean = s * (1.0f / Dd);
    const float var  = s2 * (1.0f / Dd) - mean * mean;
    const float rstd = rsqrtf(var + LN_EPS);

    const float4 g  = reinterpret_cast<const float4*>(gamma)[tid];
    const float4 be = reinterpret_cast<const float4*>(beta)[tid];
    reinterpret_cast<float4*>(O + (row << 10))[tid] = make_float4(
        (v.x - mean) * rstd * g.x + be.x,
        (v.y - mean) * rstd * g.y + be.y,
        (v.z - mean) * rstd * g.z + be.z,
        (v.w - mean) * rstd * g.w + be.w);
}

// ---------------------------------------------------------------------------
extern "C" void kernel_launch(void* const* d_in, const int* in_sizes, int n_in,
                              void* d_out, int out_size)
{
    const float* query = (const float*)d_in[0];
    const float* key   = (const float*)d_in[1];
    const float* value = (const float*)d_in[2];
    const float* Wq    = (const float*)d_in[3];
    const float* Wk    = (const float*)d_in[4];
    const float* Wv    = (const float*)d_in[5];
    const float* Wo    = (const float*)d_in[6];
    const float* gamma = (const float*)d_in[7];
    const float* beta  = (const float*)d_in[8];

    float* out  = (float*)d_out;
    float* attn = out + (long long)SD;

    float *QKV, *Vt, *Cc, *Pre, *WT;
    cudaGetSymbolAddress((void**)&QKV, g_QKV);
    cudaGetSymbolAddress((void**)&Vt,  g_Vt);
    cudaGetSymbolAddress((void**)&Cc,  g_concat);
    cudaGetSymbolAddress((void**)&Pre, g_pre);
    cudaGetSymbolAddress((void**)&WT,  g_WT);

    constexpr int PAD = 36;
    const int SM128 = 3 * (128 * PAD + 128 * PAD) * 4;  // 110592
    cudaFuncSetAttribute(mma_gemm<128, 128>, cudaFuncAttributeMaxDynamicSharedMemorySize, SM128);
    cudaFuncSetAttribute(fused_attn, cudaFuncAttributeMaxDynamicSharedMemorySize, FUSED_SMEM);

    // 0. transpose + round weights
    transpose_w_k<<<dim3(32, 32, 4), dim3(32, 8)>>>(Wq, Wk, Wv, Wo, WT);

    // 1. merged QKV projections in one launch
    mma_gemm<128, 128><<<dim3(8, 32, 3), 256, SM128>>>(
        query, key, value, Dd,
        WT, Dd, (long long)Dd * Dd,
        QKV, Dd, (long long)SD, nullptr, 1.f, 32);

    // 2. V -> Vt (K-contig for PV)
    transpose_v_k<<<dim3(32, 32, Bb), dim3(32, 8)>>>(QKV + 2ll * SD, Vt);

    // 3. fused scores + causal softmax + PV (+ upper-triangle zero-fill)
    fused_attn<<<dim3(Hh * Bb, 8), 256, FUSED_SMEM>>>(
        QKV, QKV + (long long)SD, Vt, attn, Cc);

    // 4. out-proj + residual
    mma_gemm<128, 128><<<dim3(8, 32, 1), 256, SM128>>>(
        Cc, nullptr, nullptr, Dd,
        WT + 3ll * Dd * Dd, Dd, 0, Pre, Dd, 0, query, 1.f, 32);

    // 5. layernorm
    layernorm_k<<<Bb * Ss, 256>>>(Pre, gamma, beta, out);
}